// round 4
// baseline (speedup 1.0000x reference)
#include <cuda_runtime.h>
#include <cstdint>

// PatchSampler: out[b,c,i,j] = bchw[b, c, iy[j], ix[i]], nearest = round-half-
// even of (center-16+k-0.5) = (center-16+k) & ~1, zero padding outside 1024^2.
//
// Round 4: floor-confirmed design. Timed-loop working set is L2-resident, so
// the kernel is 2 serial L2 hits + tail (~1-2us) under a ~5us graph-replay
// floor. Best-measured body (round-2 scalar direct gather, block 1024) with
// the dependent chain minimized: center loads issue first, all address math
// (including the store address) overlaps hop-1 latency, and the only
// instruction after the gather returns is the STG.

#define PS_C  128
#define PS_HW 1024
#define PS_R  16

__global__ __launch_bounds__(1024, 2)
void patch_sampler_kernel(const float* __restrict__ bchw,
                          const int*   __restrict__ centers,
                          float*       __restrict__ out)
{
    const int bc = blockIdx.x;                 // 0 .. 255
    const int b  = bc >> 7;
    const int c  = bc & 127;

    // hop 1: two independent LDGs, issued immediately
    const int cx = __ldg(&centers[b * (2 * PS_C) + c]);
    const int cy = __ldg(&centers[b * (2 * PS_C) + PS_C + c]);

    // overlaps hop-1 latency: decode + store address
    const int t = threadIdx.x;
    const int i = t >> 5;                      // output dim 2 (x)
    const int j = t & 31;                      // output dim 3 (y), lane-fast
    float* __restrict__ dst = out + ((size_t)bc << 10) + t;
    const float* __restrict__ img = bchw + ((size_t)bc << 20);

    // round-half-even of (n - 0.5) for integer n = n & ~1
    const int ix = (cx - PS_R + i) & ~1;
    const int iy = (cy - PS_R + j) & ~1;

    // hop 2: gather (predicated, zero padding)
    float v = 0.0f;
    if ((unsigned)ix < (unsigned)PS_HW && (unsigned)iy < (unsigned)PS_HW)
        v = __ldg(img + ((size_t)iy << 10) + ix);

    *dst = v;                                  // coalesced 128B per warp
}

extern "C" void kernel_launch(void* const* d_in, const int* in_sizes, int n_in,
                              void* d_out, int out_size)
{
    const float* bchw    = (const float*)d_in[0];
    const int*   centers = (const int*)d_in[1];
    float*       out     = (float*)d_out;

    patch_sampler_kernel<<<2 * PS_C, 1024>>>(bchw, centers, out);
}